// round 8
// baseline (speedup 1.0000x reference)
#include <cuda_runtime.h>

typedef unsigned long long u64;

#define CH_IN 32
#define CH_Y  16
#define WDIM  256
#define PLANE (256*256)
#define ROWS_PER_CTA 2
#define NTHR 128            // one row: thread t owns w = 2t, 2t+1

__constant__ float cWq[CH_Y*CH_IN];
__constant__ float cWk[CH_Y*CH_IN];
__constant__ float cWv[CH_Y*CH_IN];
__constant__ float cWy[CH_IN*CH_Y];
__constant__ float cbq[CH_Y];
__constant__ float cbk[CH_Y];
__constant__ float cbv[CH_Y];
__constant__ float cby[CH_IN];

__device__ __forceinline__ u64 pack2(float lo, float hi) {
    u64 r; asm("mov.b64 %0, {%1, %2};" : "=l"(r) : "f"(lo), "f"(hi)); return r;
}
__device__ __forceinline__ u64 dup2(float w) {
    u64 r; asm("mov.b64 %0, {%1, %1};" : "=l"(r) : "f"(w)); return r;
}
__device__ __forceinline__ void ffma2(u64& d, u64 a, u64 b) {
    asm("fma.rn.f32x2 %0, %1, %2, %0;" : "+l"(d) : "l"(a), "l"(b));
}
__device__ __forceinline__ u64 mul2(u64 a, u64 b) {
    u64 r; asm("mul.rn.f32x2 %0, %1, %2;" : "=l"(r) : "l"(a), "l"(b)); return r;
}
__device__ __forceinline__ float lo2(u64 v) {
    float lo, hi; asm("mov.b64 {%0, %1}, %2;" : "=f"(lo), "=f"(hi) : "l"(v)); return lo;
}
__device__ __forceinline__ float hi2(u64 v) {
    float lo, hi; asm("mov.b64 {%0, %1}, %2;" : "=f"(lo), "=f"(hi) : "l"(v)); return hi;
}

__global__ __launch_bounds__(NTHR, 3)
void cross_modal_attn_kernel(
    const float* __restrict__ c,  const float* __restrict__ p,
    float* __restrict__ out)
{
    const int tid  = threadIdx.x;      // 0..127; pixels w=2tid, 2tid+1
    const int lane = tid & 31, warp = tid >> 5;
    const int b    = blockIdx.y;

    __shared__ float sred[CH_Y][5];    // [channel][warp], 4 warps + pad
    __shared__ float sfin[CH_Y];

    const float4* cWq4 = (const float4*)cWq;
    const float4* cWk4 = (const float4*)cWk;
    const float4* cWv4 = (const float4*)cWv;
    const float4* cWy4 = (const float4*)cWy;

    for (int r = 0; r < ROWS_PER_CTA; r++) {
        const int h = blockIdx.x * ROWS_PER_CTA + r;
        const size_t base_in2  = (((size_t)b * CH_IN) * PLANE + (size_t)h * WDIM) / 2 + tid;
        const size_t base_out2 = (((size_t)b * (2*CH_IN)) * PLANE + (size_t)h * WDIM) / 2 + tid;
        const float2* p2 = (const float2*)p;
        const float2* c2 = (const float2*)c;
        float2* o2 = (float2*)out;

        // ---- phase 1: p -> k,v (pixel-pair packed), 2 chunks of 16 ci ----
        u64 kk[CH_Y], vv[CH_Y];
#pragma unroll
        for (int cy = 0; cy < CH_Y; cy++) { kk[cy] = dup2(cbk[cy]); vv[cy] = dup2(cbv[cy]); }

#pragma unroll
        for (int ch = 0; ch < 2; ch++) {
            u64 xp[16];
#pragma unroll
            for (int j = 0; j < 16; j++) {
                float2 v2 = __ldcs(p2 + base_in2 + (size_t)(ch*16 + j) * (PLANE/2));
                xp[j] = pack2(v2.x, v2.y);
            }
#pragma unroll
            for (int cy = 0; cy < CH_Y; cy++) {
#pragma unroll
                for (int j4 = 0; j4 < 4; j4++) {
                    const float4 wk = cWk4[cy*(CH_IN/4) + ch*4 + j4];
                    ffma2(kk[cy], dup2(wk.x), xp[4*j4+0]);
                    ffma2(kk[cy], dup2(wk.y), xp[4*j4+1]);
                    ffma2(kk[cy], dup2(wk.z), xp[4*j4+2]);
                    ffma2(kk[cy], dup2(wk.w), xp[4*j4+3]);
                    const float4 wv = cWv4[cy*(CH_IN/4) + ch*4 + j4];
                    ffma2(vv[cy], dup2(wv.x), xp[4*j4+0]);
                    ffma2(vv[cy], dup2(wv.y), xp[4*j4+1]);
                    ffma2(vv[cy], dup2(wv.z), xp[4*j4+2]);
                    ffma2(vv[cy], dup2(wv.w), xp[4*j4+3]);
                }
            }
        }

        // ---- phase 2: c -> q (packed) + concat copy ----
        u64 aq[CH_Y];
#pragma unroll
        for (int cy = 0; cy < CH_Y; cy++) aq[cy] = dup2(cbq[cy]);

#pragma unroll
        for (int ch = 0; ch < 2; ch++) {
            u64 xp[16];
#pragma unroll
            for (int j = 0; j < 16; j++) {
                float2 v2 = __ldcs(c2 + base_in2 + (size_t)(ch*16 + j) * (PLANE/2));
                xp[j] = pack2(v2.x, v2.y);
            }
#pragma unroll
            for (int j = 0; j < 16; j++) {
                float2 w2; w2.x = lo2(xp[j]); w2.y = hi2(xp[j]);
                __stcs(o2 + base_out2 + (size_t)(CH_IN + ch*16 + j) * (PLANE/2), w2);
            }
#pragma unroll
            for (int cy = 0; cy < CH_Y; cy++) {
#pragma unroll
                for (int j4 = 0; j4 < 4; j4++) {
                    const float4 wq = cWq4[cy*(CH_IN/4) + ch*4 + j4];
                    ffma2(aq[cy], dup2(wq.x), xp[4*j4+0]);
                    ffma2(aq[cy], dup2(wq.y), xp[4*j4+1]);
                    ffma2(aq[cy], dup2(wq.z), xp[4*j4+2]);
                    ffma2(aq[cy], dup2(wq.w), xp[4*j4+3]);
                }
            }
        }

        // ---- t = exp(q*k), packed halves; no max-subtraction (|q*k|<~12) ----
#pragma unroll
        for (int cy = 0; cy < CH_Y; cy++) {
            u64 qk = mul2(aq[cy], kk[cy]);
            aq[cy] = pack2(__expf(lo2(qk)), __expf(hi2(qk)));
        }

        // ---- row sum over 256 pixels: pair-halves + 128 threads (4 warps) ----
#pragma unroll
        for (int cy = 0; cy < CH_Y; cy++) {
            float s = lo2(aq[cy]) + hi2(aq[cy]);
#pragma unroll
            for (int o = 16; o; o >>= 1) s += __shfl_xor_sync(0xffffffffu, s, o);
            if (lane == 0) sred[cy][warp] = s;
        }
        __syncthreads();
        if (tid < CH_Y) {
            float s = sred[tid][0] + sred[tid][1] + sred[tid][2] + sred[tid][3];
            sfin[tid] = 1.0f / s;
        }
        __syncthreads();

        // y = t * rinv * v   (packed)
        u64 yp[CH_Y];
#pragma unroll
        for (int cy = 0; cy < CH_Y; cy++)
            yp[cy] = mul2(mul2(aq[cy], dup2(sfin[cy])), vv[cy]);
        if (r + 1 < ROWS_PER_CTA) __syncthreads();  // protect sred reuse

        // ---- output conv 16->32, packed over pixel pair ----
#pragma unroll
        for (int co = 0; co < CH_IN; co++) {
            u64 acc = dup2(cby[co]);
#pragma unroll
            for (int j4 = 0; j4 < CH_Y/4; j4++) {
                const float4 wy = cWy4[co*(CH_Y/4) + j4];
                ffma2(acc, dup2(wy.x), yp[4*j4+0]);
                ffma2(acc, dup2(wy.y), yp[4*j4+1]);
                ffma2(acc, dup2(wy.z), yp[4*j4+2]);
                ffma2(acc, dup2(wy.w), yp[4*j4+3]);
            }
            float2 w2; w2.x = lo2(acc); w2.y = hi2(acc);
            __stcs(o2 + base_out2 + (size_t)co * (PLANE/2), w2);
        }
    }
}

extern "C" void kernel_launch(void* const* d_in, const int* in_sizes, int n_in,
                              void* d_out, int out_size)
{
    const float* c  = (const float*)d_in[0];
    const float* p  = (const float*)d_in[1];

    // stage weights into __constant__ (D2D async memcpy nodes — graph-capturable)
    cudaMemcpyToSymbolAsync(cWq, d_in[2], CH_Y*CH_IN*sizeof(float), 0, cudaMemcpyDeviceToDevice);
    cudaMemcpyToSymbolAsync(cbq, d_in[3], CH_Y*sizeof(float),       0, cudaMemcpyDeviceToDevice);
    cudaMemcpyToSymbolAsync(cWk, d_in[4], CH_Y*CH_IN*sizeof(float), 0, cudaMemcpyDeviceToDevice);
    cudaMemcpyToSymbolAsync(cbk, d_in[5], CH_Y*sizeof(float),       0, cudaMemcpyDeviceToDevice);
    cudaMemcpyToSymbolAsync(cWv, d_in[6], CH_Y*CH_IN*sizeof(float), 0, cudaMemcpyDeviceToDevice);
    cudaMemcpyToSymbolAsync(cbv, d_in[7], CH_Y*sizeof(float),       0, cudaMemcpyDeviceToDevice);
    cudaMemcpyToSymbolAsync(cWy, d_in[8], CH_IN*CH_Y*sizeof(float), 0, cudaMemcpyDeviceToDevice);
    cudaMemcpyToSymbolAsync(cby, d_in[9], CH_IN*sizeof(float),      0, cudaMemcpyDeviceToDevice);

    float* out = (float*)d_out;
    dim3 grid(WDIM / ROWS_PER_CTA, 16);  // (128, 16) = 2048 CTAs
    dim3 block(NTHR);                    // 128 threads = one row of pixel pairs
    cross_modal_attn_kernel<<<grid, block>>>(c, p, out);
}

// round 9
// speedup vs baseline: 1.8810x; 1.8810x over previous
#include <cuda_runtime.h>

typedef unsigned long long u64;

#define CH_IN 32
#define CH_Y  16
#define WDIM  256
#define PLANE (256*256)
#define NTHR 128            // one row: thread t owns w = 2t, 2t+1

__device__ __forceinline__ u64 pack2(float lo, float hi) {
    u64 r; asm("mov.b64 %0, {%1, %2};" : "=l"(r) : "f"(lo), "f"(hi)); return r;
}
__device__ __forceinline__ u64 dup2(float w) {
    u64 r; asm("mov.b64 %0, {%1, %1};" : "=l"(r) : "f"(w)); return r;
}
__device__ __forceinline__ void ffma2(u64& d, u64 a, u64 b) {
    asm("fma.rn.f32x2 %0, %1, %2, %0;" : "+l"(d) : "l"(a), "l"(b));
}
__device__ __forceinline__ u64 mul2(u64 a, u64 b) {
    u64 r; asm("mul.rn.f32x2 %0, %1, %2;" : "=l"(r) : "l"(a), "l"(b)); return r;
}
__device__ __forceinline__ float lo2(u64 v) {
    float lo, hi; asm("mov.b64 {%0, %1}, %2;" : "=f"(lo), "=f"(hi) : "l"(v)); return lo;
}
__device__ __forceinline__ float hi2(u64 v) {
    float lo, hi; asm("mov.b64 {%0, %1}, %2;" : "=f"(lo), "=f"(hi) : "l"(v)); return hi;
}

__global__ __launch_bounds__(NTHR, 4)
void cross_modal_attn_kernel(
    const float* __restrict__ c,  const float* __restrict__ p,
    const float* __restrict__ Wq, const float* __restrict__ bq,
    const float* __restrict__ Wk, const float* __restrict__ bk,
    const float* __restrict__ Wv, const float* __restrict__ bv,
    const float* __restrict__ Wy, const float* __restrict__ by,
    float* __restrict__ out)
{
    const int tid  = threadIdx.x;      // 0..127; pixels w=2tid, 2tid+1
    const int lane = tid & 31, warp = tid >> 5;
    const int h    = blockIdx.x;
    const int b    = blockIdx.y;

    __shared__ float4 sWq[CH_Y*CH_IN/4], sWk[CH_Y*CH_IN/4], sWv[CH_Y*CH_IN/4];
    __shared__ float4 sWy[CH_IN*CH_Y/4];
    __shared__ float sbq[CH_Y], sbk[CH_Y], sbv[CH_Y], sby[CH_IN];
    __shared__ float sred[CH_Y][5];    // [channel][warp], 4 warps + pad
    __shared__ float sfin[CH_Y];

    {
        float* dWq = (float*)sWq; float* dWk = (float*)sWk;
        float* dWv = (float*)sWv; float* dWy = (float*)sWy;
        for (int i = tid; i < CH_Y*CH_IN; i += NTHR) {
            dWq[i] = Wq[i]; dWk[i] = Wk[i]; dWv[i] = Wv[i]; dWy[i] = Wy[i];
        }
    }
    if (tid < CH_Y)  { sbq[tid] = bq[tid]; sbk[tid] = bk[tid]; sbv[tid] = bv[tid]; }
    if (tid < CH_IN) { sby[tid] = by[tid]; }
    __syncthreads();

    const size_t base_in2  = (((size_t)b * CH_IN) * PLANE + (size_t)h * WDIM) / 2 + tid;
    const size_t base_out2 = (((size_t)b * (2*CH_IN)) * PLANE + (size_t)h * WDIM) / 2 + tid;
    const float2* p2 = (const float2*)p;
    const float2* c2 = (const float2*)c;
    float2* o2 = (float2*)out;

    // ---- Phase A: c -> q (pixel-pair packed) + concat copy; chunks of 16 ci ----
    u64 aq[CH_Y];
#pragma unroll
    for (int cy = 0; cy < CH_Y; cy++) aq[cy] = dup2(sbq[cy]);

#pragma unroll
    for (int ch = 0; ch < 2; ch++) {
        u64 xc[16];
#pragma unroll
        for (int j = 0; j < 16; j++) {
            float2 v2 = __ldcs(c2 + base_in2 + (size_t)(ch*16 + j) * (PLANE/2));
            xc[j] = pack2(v2.x, v2.y);
        }
#pragma unroll
        for (int j = 0; j < 16; j++) {
            float2 w2; w2.x = lo2(xc[j]); w2.y = hi2(xc[j]);
            __stcs(o2 + base_out2 + (size_t)(CH_IN + ch*16 + j) * (PLANE/2), w2);
        }
#pragma unroll
        for (int cy = 0; cy < CH_Y; cy++) {
#pragma unroll
            for (int j4 = 0; j4 < 4; j4++) {
                const float4 wq = sWq[cy*(CH_IN/4) + ch*4 + j4];
                ffma2(aq[cy], dup2(wq.x), xc[4*j4+0]);
                ffma2(aq[cy], dup2(wq.y), xc[4*j4+1]);
                ffma2(aq[cy], dup2(wq.z), xc[4*j4+2]);
                ffma2(aq[cy], dup2(wq.w), xc[4*j4+3]);
            }
        }
    }

    // ---- Phase B: load ALL p channels (MLP=32), keep live through E ----
    u64 xp[CH_IN];
#pragma unroll
    for (int j = 0; j < CH_IN; j++) {
        float2 v2 = __ldcs(p2 + base_in2 + (size_t)j * (PLANE/2));
        xp[j] = pack2(v2.x, v2.y);
    }

    // ---- Phase C: per-channel k on the fly, t = exp(q*k) in place ----
    // (no max-subtraction: |q*k| <~ 12, fp32 exp safe; normalization identical)
#pragma unroll
    for (int cy = 0; cy < CH_Y; cy++) {
        u64 kcy = dup2(sbk[cy]);
#pragma unroll
        for (int j4 = 0; j4 < CH_IN/4; j4++) {
            const float4 wk = sWk[cy*(CH_IN/4) + j4];
            ffma2(kcy, dup2(wk.x), xp[4*j4+0]);
            ffma2(kcy, dup2(wk.y), xp[4*j4+1]);
            ffma2(kcy, dup2(wk.z), xp[4*j4+2]);
            ffma2(kcy, dup2(wk.w), xp[4*j4+3]);
        }
        u64 qk = mul2(aq[cy], kcy);
        aq[cy] = pack2(__expf(lo2(qk)), __expf(hi2(qk)));
    }

    // ---- Phase D: row sum over 256 pixels (pair halves + 4 warps) ----
#pragma unroll
    for (int cy = 0; cy < CH_Y; cy++) {
        float s = lo2(aq[cy]) + hi2(aq[cy]);
#pragma unroll
        for (int o = 16; o; o >>= 1) s += __shfl_xor_sync(0xffffffffu, s, o);
        if (lane == 0) sred[cy][warp] = s;
    }
    __syncthreads();
    if (tid < CH_Y) {
        float s = sred[tid][0] + sred[tid][1] + sred[tid][2] + sred[tid][3];
        sfin[tid] = 1.0f / s;
    }
    __syncthreads();

    // ---- Phase E: per-channel v on the fly (xp still live), yp in place ----
#pragma unroll
    for (int cy = 0; cy < CH_Y; cy++) {
        u64 vcy = dup2(sbv[cy]);
#pragma unroll
        for (int j4 = 0; j4 < CH_IN/4; j4++) {
            const float4 wv = sWv[cy*(CH_IN/4) + j4];
            ffma2(vcy, dup2(wv.x), xp[4*j4+0]);
            ffma2(vcy, dup2(wv.y), xp[4*j4+1]);
            ffma2(vcy, dup2(wv.z), xp[4*j4+2]);
            ffma2(vcy, dup2(wv.w), xp[4*j4+3]);
        }
        aq[cy] = mul2(mul2(aq[cy], dup2(sfin[cy])), vcy);
    }

    // ---- Phase F: output conv 16->32, packed over pixel pair ----
#pragma unroll
    for (int co = 0; co < CH_IN; co++) {
        u64 acc = dup2(sby[co]);
#pragma unroll
        for (int j4 = 0; j4 < CH_Y/4; j4++) {
            const float4 wy = sWy[co*(CH_Y/4) + j4];
            ffma2(acc, dup2(wy.x), aq[4*j4+0]);
            ffma2(acc, dup2(wy.y), aq[4*j4+1]);
            ffma2(acc, dup2(wy.z), aq[4*j4+2]);
            ffma2(acc, dup2(wy.w), aq[4*j4+3]);
        }
        float2 w2; w2.x = lo2(acc); w2.y = hi2(acc);
        __stcs(o2 + base_out2 + (size_t)co * (PLANE/2), w2);
    }
}

extern "C" void kernel_launch(void* const* d_in, const int* in_sizes, int n_in,
                              void* d_out, int out_size)
{
    const float* c  = (const float*)d_in[0];
    const float* p  = (const float*)d_in[1];
    const float* Wq = (const float*)d_in[2];
    const float* bq = (const float*)d_in[3];
    const float* Wk = (const float*)d_in[4];
    const float* bk = (const float*)d_in[5];
    const float* Wv = (const float*)d_in[6];
    const float* bv = (const float*)d_in[7];
    const float* Wy = (const float*)d_in[8];
    const float* by = (const float*)d_in[9];
    float* out = (float*)d_out;

    dim3 grid(WDIM, 16);   // (256, 16) = 4096 CTAs, one row each
    dim3 block(NTHR);      // 128 threads = one row of pixel pairs
    cross_modal_attn_kernel<<<grid, block>>>(c, p, Wq, bq, Wk, bk, Wv, bv, Wy, by, out);
}